// round 15
// baseline (speedup 1.0000x reference)
#include <cuda_runtime.h>
#include <cuda_fp16.h>
#include <cstdint>

#define VOCAB  32000
#define EMBED  256
#define HIDDEN 512
#define BATCH  64
#define TCAP   32
#define SEQ    33                 // T_CAP + 1
#define MROWS  (SEQ*BATCH)        // 2112
#define MPAD   2304               // 9*256 (GEMM M padding)
#define G4     (4*HIDDEN)         // 2048
#define OUT_SV (SEQ*VOCAB)        // 1056000

// ---- LSTM persistent config (fp16 smem) ----
#define NCTA   64
#define JW     8
#define PR     32
#define LSW    520                // half stride; 1040B/row -> +4 bank skew
#define LS_HH  (PR*LSW)           // sH offset in halfs
#define LS_GB  ((LS_HH + 64*LSW)*2)   // sG byte offset = 99840
#define LS_BYTES (LS_GB + 64*36*4)    // 109056

// ---- GEMM config: CTA 256(M) x 128(N), 8 warps of 64x64, 3-stage ----
#define SRH    72                 // half stride per row (144B)
#define ASTGB  (256*SRH*2)        // 36864 B
#define BSTGB  (128*SRH*2)        // 18432 B
#define STAGEB (ASTGB+BSTGB)      // 55296 B
#define NSTAGE 3
#define GEMM_SMEM_BYTES (NSTAGE*STAGEB)   // 165888 B

// ---------------- scratch (static device globals; no allocation) -------------
__device__ __align__(16) __half d_xg[MPAD*EMBED];     // gathered inputs fp16
__device__ float  d_xproj[MROWS*G4];
__device__ __align__(16) __half d_hs[MPAD*HIDDEN];    // hidden states fp16
__device__ __align__(16) __half d_wih_h[G4*EMBED];
__device__ __align__(16) __half d_wout_h[VOCAB*HIDDEN];
__device__ unsigned d_bar[SEQ];

// ---------------- helpers ----------------------------------------------------
__device__ __forceinline__ void mma_f16(float c[4], const unsigned a[4], const unsigned b[2]) {
    asm volatile(
        "mma.sync.aligned.m16n8k16.row.col.f32.f16.f16.f32 "
        "{%0,%1,%2,%3},{%4,%5,%6,%7},{%8,%9},{%0,%1,%2,%3};\n"
        : "+f"(c[0]), "+f"(c[1]), "+f"(c[2]), "+f"(c[3])
        : "r"(a[0]), "r"(a[1]), "r"(a[2]), "r"(a[3]), "r"(b[0]), "r"(b[1]));
}

__device__ __forceinline__ void ldsm4(unsigned r[4], unsigned addr) {
    asm volatile("ldmatrix.sync.aligned.m8n8.x4.shared.b16 {%0,%1,%2,%3}, [%4];"
                 : "=r"(r[0]), "=r"(r[1]), "=r"(r[2]), "=r"(r[3]) : "r"(addr));
}

__device__ __forceinline__ unsigned smem_u32(const void* p) {
    return (unsigned)__cvta_generic_to_shared(p);
}
__device__ __forceinline__ void cp16(unsigned dst, const void* src) {
    asm volatile("cp.async.cg.shared.global [%0], [%1], 16;" :: "r"(dst), "l"(src));
}
#define CP_COMMIT() asm volatile("cp.async.commit_group;")
#define CP_WAIT(n)  asm volatile("cp.async.wait_group %0;" :: "n"(n))

__device__ __forceinline__ unsigned ld_acq(const unsigned* p) {
    unsigned v;
    asm volatile("ld.acquire.gpu.global.u32 %0, [%1];" : "=r"(v) : "l"(p));
    return v;
}
__device__ __forceinline__ float sigf(float x) { return 1.0f / (1.0f + expf(-x)); }

// ---------------- small prep kernels -----------------------------------------
__global__ void bar_reset() {
    if (threadIdx.x < SEQ) d_bar[threadIdx.x] = 0;
}

__global__ void roundh(const float* __restrict__ src, __half* __restrict__ dst, int n4) {
    int i = blockIdx.x * blockDim.x + threadIdx.x;
    if (i < n4) {
        float4 v = ((const float4*)src)[i];
        __half2 a = __floats2half2_rn(v.x, v.y);
        __half2 b = __floats2half2_rn(v.z, v.w);
        ((__half2*)dst)[2 * i]     = a;
        ((__half2*)dst)[2 * i + 1] = b;
    }
}

__global__ void gather_kernel(const float* __restrict__ features,
                              const int*   __restrict__ captions,
                              const float* __restrict__ embedding) {
    int m = blockIdx.x;
    int s = m >> 6, b = m & 63;
    const float* src = (s == 0) ? (features + (size_t)b * EMBED)
                                : (embedding + (size_t)captions[b * TCAP + (s - 1)] * EMBED);
    __half* dst = d_xg + (size_t)m * EMBED;
    for (int i = threadIdx.x; i < EMBED; i += blockDim.x)
        dst[i] = __float2half_rn(src[i]);
}

// ---- 256x128 fp16 mma GEMM, 64x64 warp tiles, 3-stage cp.async --------------
// C = A[M,K] @ B[N,K]^T + bias (A,B fp16; accum fp32).
// mode 0: C[m*N+n] = acc + bias1[n] + bias2[n]          (x_proj)
// mode 1: out[b*OUT_SV + s*VOCAB + n] = acc + bias1[n]  (logits; m = s*64+b)
__global__ __launch_bounds__(256, 1)
void gemm_h(const __half* __restrict__ A, const __half* __restrict__ B,
            const float* __restrict__ bias1, const float* __restrict__ bias2,
            float* __restrict__ C, int M, int N, int K, int mode) {
    extern __shared__ char smc[];
    const unsigned smu = smem_u32(smc);

    const int m0 = blockIdx.y * 256, n0 = blockIdx.x * 128;
    const int tid  = threadIdx.x;
    const int warp = tid >> 5, lane = tid & 31;
    const int grp  = lane >> 2, tig = lane & 3;
    const int wm = warp & 3, wn = warp >> 2;        // 4 warps M x 2 warps N
    const int mb = wm * 64, nb = wn * 64;           // warp tile 64x64

    // ldmatrix per-thread offsets (halfs)
    const int aoff = (lane & 15) * SRH + (lane >> 4) * 8;
    const int boff = ((lane & 7) + ((lane >> 4) << 3)) * SRH + ((lane >> 3) & 1) * 8;

    float acc[4][8][4];
    #pragma unroll
    for (int mt = 0; mt < 4; mt++)
        #pragma unroll
        for (int nt = 0; nt < 8; nt++)
            #pragma unroll
            for (int q = 0; q < 4; q++) acc[mt][nt][q] = 0.0f;

    const int r_st = tid >> 3;              // 0..31
    const int c16  = tid & 7;               // 16B chunk in 64-half row

    auto stage = [&](int buf, int kc) {
        unsigned abase = smu + (unsigned)buf * STAGEB;
        unsigned bbase = abase + ASTGB;
        const __half* Ap = A + (size_t)m0 * K + (size_t)kc * 64 + c16 * 8;
        const __half* Bp = B + (size_t)n0 * K + (size_t)kc * 64 + c16 * 8;
        #pragma unroll
        for (int i = 0; i < 8; i++) {       // A: 256 rows
            int r = r_st + i * 32;
            cp16(abase + (unsigned)(r * SRH + c16 * 8) * 2, Ap + (size_t)r * K);
        }
        #pragma unroll
        for (int i = 0; i < 4; i++) {       // B: 128 rows
            int r = r_st + i * 32;
            cp16(bbase + (unsigned)(r * SRH + c16 * 8) * 2, Bp + (size_t)r * K);
        }
    };

    const int nk = K >> 6;
    stage(0, 0); CP_COMMIT();
    if (nk > 1) { stage(1, 1); CP_COMMIT(); }

    for (int kc = 0; kc < nk; kc++) {
        if (kc + 1 < nk) { CP_WAIT(1); } else { CP_WAIT(0); }
        __syncthreads();
        if (kc + 2 < nk) { stage((kc + 2) % NSTAGE, kc + 2); CP_COMMIT(); }

        const unsigned cAu = smu + (unsigned)(kc % NSTAGE) * STAGEB;
        const unsigned cBu = cAu + ASTGB;
        #pragma unroll
        for (int ks = 0; ks < 64; ks += 16) {
            unsigned af[4][4];
            unsigned bf[4][4];
            #pragma unroll
            for (int mt = 0; mt < 4; mt++)
                ldsm4(af[mt], cAu + (unsigned)((mb + mt * 16) * SRH + ks + aoff) * 2);
            #pragma unroll
            for (int p = 0; p < 4; p++)
                ldsm4(bf[p], cBu + (unsigned)((nb + p * 16) * SRH + ks + boff) * 2);
            #pragma unroll
            for (int mt = 0; mt < 4; mt++)
                #pragma unroll
                for (int nt = 0; nt < 8; nt++)
                    mma_f16(acc[mt][nt], af[mt], &bf[nt >> 1][(nt & 1) * 2]);
        }
        __syncthreads();
    }

    // epilogue
    #pragma unroll
    for (int mt = 0; mt < 4; mt++) {
        #pragma unroll
        for (int nt = 0; nt < 8; nt++) {
            int rA = m0 + mb + mt * 16 + grp;
            int rB = rA + 8;
            int n  = n0 + nb + nt * 8 + 2 * tig;
            float bv0 = bias1[n];
            float bv1 = bias1[n + 1];
            if (bias2) { bv0 += bias2[n]; bv1 += bias2[n + 1]; }
            if (mode == 0) {
                if (rA < M) {
                    C[(size_t)rA * N + n]     = acc[mt][nt][0] + bv0;
                    C[(size_t)rA * N + n + 1] = acc[mt][nt][1] + bv1;
                }
                if (rB < M) {
                    C[(size_t)rB * N + n]     = acc[mt][nt][2] + bv0;
                    C[(size_t)rB * N + n + 1] = acc[mt][nt][3] + bv1;
                }
            } else {
                if (rA < M) {
                    int s = rA >> 6, b = rA & 63;
                    size_t o = (size_t)b * OUT_SV + (size_t)s * VOCAB + n;
                    C[o]     = acc[mt][nt][0] + bv0;
                    C[o + 1] = acc[mt][nt][1] + bv1;
                }
                if (rB < M) {
                    int s = rB >> 6, b = rB & 63;
                    size_t o = (size_t)b * OUT_SV + (size_t)s * VOCAB + n;
                    C[o]     = acc[mt][nt][2] + bv0;
                    C[o + 1] = acc[mt][nt][3] + bv1;
                }
            }
        }
    }
}

// ---------------- persistent LSTM (fp16 data path, unchanged from R13) --------
__global__ __launch_bounds__(256, 1)
void lstm_persist(const float* __restrict__ Whh) {
    extern __shared__ char smc[];
    __half* sW = (__half*)smc;                  // [32][520]
    float*  sG = (float*)(smc + LS_GB);         // [64][36]
    const unsigned smu = smem_u32(smc);

    const int j0   = blockIdx.x * JW;
    const int tid  = threadIdx.x;
    const int warp = tid >> 5, lane = tid & 31;
    const int grp  = lane >> 2, tig = lane & 3;
    const int wm = warp & 3;        // m16 tile rows: wm*16
    const int wn = warp >> 2;       // packed cols:   wn*16 (2 n8 tiles)

    const int aoff = (lane & 15) * LSW + (lane >> 4) * 8;
    const int boff = ((lane & 7) + ((lane >> 4) << 3)) * LSW + ((lane >> 3) & 1) * 8;

    // stage W_hh slice (fp16), once
    for (int idx = tid; idx < PR * 128; idx += 256) {
        int p  = idx >> 7;
        int c4 = (idx & 127) << 2;
        int g  = (p & 3) * HIDDEN + j0 + (p >> 2);
        float4 v = *(const float4*)(Whh + (size_t)g * HIDDEN + c4);
        __half* dw = sW + p * LSW + c4;
        dw[0] = __float2half_rn(v.x); dw[1] = __float2half_rn(v.y);
        dw[2] = __float2half_rn(v.z); dw[3] = __float2half_rn(v.w);
    }
    __syncthreads();

    float cst[2] = {0.f, 0.f};

    #pragma unroll 1
    for (int t = 0; t < SEQ; t++) {
        float pg[2][4];
        #pragma unroll
        for (int it = 0; it < 2; it++) {
            int id = tid + it * 256;
            int jl = id & 7, b = id >> 3;
            const float* xp = d_xproj + ((size_t)(t * BATCH + b)) * G4 + j0 + jl;
            pg[it][0] = xp[0];
            pg[it][1] = xp[HIDDEN];
            pg[it][2] = xp[2 * HIDDEN];
            pg[it][3] = xp[3 * HIDDEN];
        }

        float acc[2][4];
        #pragma unroll
        for (int nt = 0; nt < 2; nt++)
            #pragma unroll
            for (int q = 0; q < 4; q++) acc[nt][q] = 0.0f;

        if (t > 0) {
            const __half* A = d_hs + (size_t)(t - 1) * BATCH * HIDDEN;
            // stage h tile (64 rows x 512 halfs) in two halves via cp.async
            #pragma unroll
            for (int half = 0; half < 2; half++) {
                #pragma unroll
                for (int i = 0; i < 8; i++) {
                    int lin = tid + i * 256;           // 0..2047
                    int r = lin >> 5, c16 = lin & 31;  // 64 rows x 32 chunks
                    unsigned dst = smu + (unsigned)(LS_HH + r * LSW + half * 256 + c16 * 8) * 2;
                    cp16(dst, A + (size_t)r * HIDDEN + half * 256 + c16 * 8);
                }
                CP_COMMIT();
            }

            auto mma_half = [&](int half) {
                const int hk = half * 256;
                #pragma unroll
                for (int ks = 0; ks < 256; ks += 16) {
                    unsigned af[4], bf[4];
                    ldsm4(af, smu + (unsigned)(LS_HH + (wm * 16) * LSW + hk + ks + aoff) * 2);
                    ldsm4(bf, smu + (unsigned)((wn * 16) * LSW + hk + ks + boff) * 2);
                    mma_f16(acc[0], af, &bf[0]);
                    mma_f16(acc[1], af, &bf[2]);
                }
            };

            CP_WAIT(1); __syncthreads();
            mma_half(0);
            CP_WAIT(0); __syncthreads();
            mma_half(1);

            __syncthreads();
            #pragma unroll
            for (int nt = 0; nt < 2; nt++) {
                int r  = wm * 16 + grp;
                int cc = wn * 16 + nt * 8 + 2 * tig;
                sG[r * 36 + cc]           = acc[nt][0];
                sG[r * 36 + cc + 1]       = acc[nt][1];
                sG[(r + 8) * 36 + cc]     = acc[nt][2];
                sG[(r + 8) * 36 + cc + 1] = acc[nt][3];
            }
            __syncthreads();
        }

        #pragma unroll
        for (int it = 0; it < 2; it++) {
            int id = tid + it * 256;
            int jl = id & 7, b = id >> 3;
            int j  = j0 + jl;
            float gi = pg[it][0], gf = pg[it][1], gg = pg[it][2], go = pg[it][3];
            if (t > 0) {
                gi += sG[b * 36 + jl * 4 + 0];
                gf += sG[b * 36 + jl * 4 + 1];
                gg += sG[b * 36 + jl * 4 + 2];
                go += sG[b * 36 + jl * 4 + 3];
            }
            float cn = sigf(gf) * cst[it] + sigf(gi) * tanhf(gg);
            float hn = sigf(go) * tanhf(cn);
            cst[it] = cn;
            d_hs[((size_t)t * BATCH + b) * HIDDEN + j] = __float2half_rn(hn);
        }

        if (t < SEQ - 1) {
            __syncthreads();
            if (tid == 0) {
                __threadfence();
                atomicAdd(&d_bar[t], 1u);
                while (ld_acq(&d_bar[t]) < NCTA) { }
            }
            __syncthreads();
        }
    }
}

// ---------------- launch ------------------------------------------------------
extern "C" void kernel_launch(void* const* d_in, const int* in_sizes, int n_in,
                              void* d_out, int out_size) {
    const float* features  = (const float*)d_in[0];
    const int*   captions  = (const int*)  d_in[1];
    /* lengths d_in[2] unused by the reference */
    const float* embedding = (const float*)d_in[3];
    const float* W_ih      = (const float*)d_in[4];
    const float* W_hh      = (const float*)d_in[5];
    const float* b_ih      = (const float*)d_in[6];
    const float* b_hh      = (const float*)d_in[7];
    const float* W_out     = (const float*)d_in[8];
    const float* b_out     = (const float*)d_in[9];
    float* out = (float*)d_out;

    __half *xg_p, *hs_p, *wih_p, *wout_p;
    float *xproj_p;
    cudaGetSymbolAddress((void**)&xg_p,    d_xg);
    cudaGetSymbolAddress((void**)&xproj_p, d_xproj);
    cudaGetSymbolAddress((void**)&hs_p,    d_hs);
    cudaGetSymbolAddress((void**)&wih_p,   d_wih_h);
    cudaGetSymbolAddress((void**)&wout_p,  d_wout_h);

    cudaFuncSetAttribute(gemm_h,
                         cudaFuncAttributeMaxDynamicSharedMemorySize, GEMM_SMEM_BYTES);
    cudaFuncSetAttribute(lstm_persist,
                         cudaFuncAttributeMaxDynamicSharedMemorySize, LS_BYTES);

    // 1) gather x (fp16) + convert weights to fp16
    gather_kernel<<<MROWS, 256>>>(features, captions, embedding);
    roundh<<<(G4 * EMBED / 4 + 255) / 256, 256>>>(W_ih, wih_p, G4 * EMBED / 4);
    roundh<<<(VOCAB * HIDDEN / 4 + 255) / 256, 256>>>(W_out, wout_p, VOCAB * HIDDEN / 4);

    // 2) x_proj = x @ W_ih^T + b_ih + b_hh   [2112 x 2048], K=256
    {
        dim3 grid(G4 / 128, MPAD / 256);       // (16, 9) = 144 CTAs, one wave
        gemm_h<<<grid, 256, GEMM_SMEM_BYTES>>>(xg_p, wih_p, b_ih, b_hh, xproj_p,
                                               MROWS, G4, EMBED, 0);
    }

    // 3) all 33 LSTM steps in one persistent kernel
    bar_reset<<<1, 64>>>();
    lstm_persist<<<NCTA, 256, LS_BYTES>>>(W_hh);

    // 4) logits = hs @ W_out^T + b_out -> out[b][s][v]   [2112 x 32000], K=512
    {
        dim3 grid(VOCAB / 128, MPAD / 256);    // (250, 9)
        gemm_h<<<grid, 256, GEMM_SMEM_BYTES>>>(hs_p, wout_p, b_out, nullptr, out,
                                               MROWS, VOCAB, HIDDEN, 1);
    }
}

// round 16
// speedup vs baseline: 1.2856x; 1.2856x over previous
#include <cuda_runtime.h>
#include <cuda_fp16.h>
#include <cstdint>

#define VOCAB  32000
#define EMBED  256
#define HIDDEN 512
#define BATCH  64
#define TCAP   32
#define SEQ    33                 // T_CAP + 1
#define MROWS  (SEQ*BATCH)        // 2112
#define MPAD   2176               // 17*128 (GEMM M padding)
#define G4     (4*HIDDEN)         // 2048
#define OUT_SV (SEQ*VOCAB)        // 1056000

// ---- LSTM persistent config (fp16 smem) ----
#define NCTA   64
#define JW     8
#define PR     32
#define LSW    520                // half stride; 1040B/row -> +4 bank skew
#define LS_HH  (PR*LSW)           // sH offset in halfs
#define LS_GB  ((LS_HH + 64*LSW)*2)   // sG byte offset = 99840
#define LS_BYTES (LS_GB + 64*36*4)    // 109056

// ---- GEMM config (R13-proven): 128x128 tile, K-chunk 64, 2-stage ----
#define SRH    72                 // half stride per row (144B)
#define STAGEB 36864              // per stage: A 128*144 + B 128*144
#define GEMM_SMEM_BYTES (2*STAGEB)    // 73728

// ---------------- scratch (static device globals; no allocation) -------------
__device__ __align__(16) __half d_xg[MPAD*EMBED];     // gathered inputs fp16, pad rows zero
__device__ float  d_xproj[MROWS*G4];
__device__ __align__(16) __half d_hs[MPAD*HIDDEN];    // hidden states fp16, pad rows zero
__device__ float  d_c[BATCH*HIDDEN];                  // cell state across LSTM chunks
__device__ __align__(16) __half d_wih_h[G4*EMBED];
__device__ __align__(16) __half d_wout_h[VOCAB*HIDDEN];
__device__ unsigned d_bar[SEQ];

// ---------------- helpers ----------------------------------------------------
__device__ __forceinline__ void mma_f16(float c[4], const unsigned a[4], const unsigned b[2]) {
    asm volatile(
        "mma.sync.aligned.m16n8k16.row.col.f32.f16.f16.f32 "
        "{%0,%1,%2,%3},{%4,%5,%6,%7},{%8,%9},{%0,%1,%2,%3};\n"
        : "+f"(c[0]), "+f"(c[1]), "+f"(c[2]), "+f"(c[3])
        : "r"(a[0]), "r"(a[1]), "r"(a[2]), "r"(a[3]), "r"(b[0]), "r"(b[1]));
}

__device__ __forceinline__ void ldsm4(unsigned r[4], unsigned addr) {
    asm volatile("ldmatrix.sync.aligned.m8n8.x4.shared.b16 {%0,%1,%2,%3}, [%4];"
                 : "=r"(r[0]), "=r"(r[1]), "=r"(r[2]), "=r"(r[3]) : "r"(addr));
}

__device__ __forceinline__ unsigned smem_u32(const void* p) {
    return (unsigned)__cvta_generic_to_shared(p);
}
__device__ __forceinline__ void cp16(unsigned dst, const void* src) {
    asm volatile("cp.async.cg.shared.global [%0], [%1], 16;" :: "r"(dst), "l"(src));
}
#define CP_COMMIT() asm volatile("cp.async.commit_group;")
#define CP_WAIT(n)  asm volatile("cp.async.wait_group %0;" :: "n"(n))

__device__ __forceinline__ unsigned ld_acq(const unsigned* p) {
    unsigned v;
    asm volatile("ld.acquire.gpu.global.u32 %0, [%1];" : "=r"(v) : "l"(p));
    return v;
}
__device__ __forceinline__ float sigf(float x) { return 1.0f / (1.0f + expf(-x)); }

// ---------------- small prep kernels -----------------------------------------
__global__ void bar_reset() {
    if (threadIdx.x < SEQ) d_bar[threadIdx.x] = 0;
}

__global__ void roundh(const float* __restrict__ src, __half* __restrict__ dst, int n4) {
    int i = blockIdx.x * blockDim.x + threadIdx.x;
    if (i < n4) {
        float4 v = ((const float4*)src)[i];
        __half2 a = __floats2half2_rn(v.x, v.y);
        __half2 b = __floats2half2_rn(v.z, v.w);
        ((__half2*)dst)[2 * i]     = a;
        ((__half2*)dst)[2 * i + 1] = b;
    }
}

__global__ void gather_kernel(const float* __restrict__ features,
                              const int*   __restrict__ captions,
                              const float* __restrict__ embedding) {
    int m = blockIdx.x;
    int s = m >> 6, b = m & 63;
    const float* src = (s == 0) ? (features + (size_t)b * EMBED)
                                : (embedding + (size_t)captions[b * TCAP + (s - 1)] * EMBED);
    __half* dst = d_xg + (size_t)m * EMBED;
    for (int i = threadIdx.x; i < EMBED; i += blockDim.x)
        dst[i] = __float2half_rn(src[i]);
}

// ------- 128x128 fp16 mma GEMM, K-chunk 64, 2-stage (R13 config) -------------
// C = A[M,K] @ B[N,K]^T + bias (A,B fp16; accum fp32).  m0 = (ytile0+by)*128.
// mode 0: C[m*N+n] = acc + bias1[n] + bias2[n]          (x_proj)
// mode 1: out[b*OUT_SV + s*VOCAB + n] = acc + bias1[n]  (logits; m = s*64+b)
__global__ __launch_bounds__(256, 2)
void gemm_h(const __half* __restrict__ A, const __half* __restrict__ B,
            const float* __restrict__ bias1, const float* __restrict__ bias2,
            float* __restrict__ C, int M, int N, int K, int mode, int ytile0) {
    extern __shared__ char smc[];
    const unsigned smu = smem_u32(smc);

    const int m0 = (ytile0 + blockIdx.y) * 128, n0 = blockIdx.x * 128;
    const int tid  = threadIdx.x;
    const int warp = tid >> 5, lane = tid & 31;
    const int grp  = lane >> 2, tig = lane & 3;
    const int wm = warp & 1, wn = warp >> 1;        // 2 warps M x 4 warps N
    const int mb = wm * 64, nb = wn * 32;           // warp tile 64x32

    const int aoff = (lane & 15) * SRH + (lane >> 4) * 8;
    const int boff = ((lane & 7) + ((lane >> 4) << 3)) * SRH + ((lane >> 3) & 1) * 8;

    float acc[4][4][4];
    #pragma unroll
    for (int mt = 0; mt < 4; mt++)
        #pragma unroll
        for (int nt = 0; nt < 4; nt++)
            #pragma unroll
            for (int q = 0; q < 4; q++) acc[mt][nt][q] = 0.0f;

    const int r_st = tid >> 3;              // 0..31
    const int c16  = tid & 7;               // 16B chunk in 64-half row

    auto stage = [&](int buf, int kc) {
        unsigned abase = smu + (unsigned)buf * STAGEB;
        unsigned bbase = abase + 128 * SRH * 2;
        const __half* Ap = A + (size_t)m0 * K + (size_t)kc * 64 + c16 * 8;
        const __half* Bp = B + (size_t)n0 * K + (size_t)kc * 64 + c16 * 8;
        #pragma unroll
        for (int i = 0; i < 4; i++) {
            int r = r_st + i * 32;
            cp16(abase + (unsigned)(r * SRH + c16 * 8) * 2, Ap + (size_t)r * K);
            cp16(bbase + (unsigned)(r * SRH + c16 * 8) * 2, Bp + (size_t)r * K);
        }
    };

    const int nk = K >> 6;
    stage(0, 0); CP_COMMIT();

    for (int kc = 0; kc < nk; kc++) {
        CP_WAIT(0);
        __syncthreads();
        if (kc + 1 < nk) { stage((kc + 1) & 1, kc + 1); CP_COMMIT(); }

        const unsigned cAu = smu + (unsigned)(kc & 1) * STAGEB;
        const unsigned cBu = cAu + 128 * SRH * 2;
        #pragma unroll
        for (int ks = 0; ks < 64; ks += 16) {
            unsigned af[4][4];
            unsigned bf[2][4];
            #pragma unroll
            for (int mt = 0; mt < 4; mt++)
                ldsm4(af[mt], cAu + (unsigned)((mb + mt * 16) * SRH + ks + aoff) * 2);
            #pragma unroll
            for (int p = 0; p < 2; p++)
                ldsm4(bf[p], cBu + (unsigned)((nb + p * 16) * SRH + ks + boff) * 2);
            #pragma unroll
            for (int mt = 0; mt < 4; mt++)
                #pragma unroll
                for (int nt = 0; nt < 4; nt++)
                    mma_f16(acc[mt][nt], af[mt], &bf[nt >> 1][(nt & 1) * 2]);
        }
    }

    // epilogue
    #pragma unroll
    for (int mt = 0; mt < 4; mt++) {
        #pragma unroll
        for (int nt = 0; nt < 4; nt++) {
            int rA = m0 + mb + mt * 16 + grp;
            int rB = rA + 8;
            int n  = n0 + nb + nt * 8 + 2 * tig;
            float bv0 = bias1[n];
            float bv1 = bias1[n + 1];
            if (bias2) { bv0 += bias2[n]; bv1 += bias2[n + 1]; }
            if (mode == 0) {
                if (rA < M) {
                    C[(size_t)rA * N + n]     = acc[mt][nt][0] + bv0;
                    C[(size_t)rA * N + n + 1] = acc[mt][nt][1] + bv1;
                }
                if (rB < M) {
                    C[(size_t)rB * N + n]     = acc[mt][nt][2] + bv0;
                    C[(size_t)rB * N + n + 1] = acc[mt][nt][3] + bv1;
                }
            } else {
                if (rA < M) {
                    int s = rA >> 6, b = rA & 63;
                    size_t o = (size_t)b * OUT_SV + (size_t)s * VOCAB + n;
                    C[o]     = acc[mt][nt][0] + bv0;
                    C[o + 1] = acc[mt][nt][1] + bv1;
                }
                if (rB < M) {
                    int s = rB >> 6, b = rB & 63;
                    size_t o = (size_t)b * OUT_SV + (size_t)s * VOCAB + n;
                    C[o]     = acc[mt][nt][2] + bv0;
                    C[o + 1] = acc[mt][nt][3] + bv1;
                }
            }
        }
    }
}

// ---------------- persistent LSTM chunk [t0, t1) ------------------------------
// 64 CTAs; CTA owns j in [j0, j0+8). Cell state spills to d_c at chunk bounds.
__global__ __launch_bounds__(256, 1)
void lstm_persist(const float* __restrict__ Whh, int t0, int t1) {
    extern __shared__ char smc[];
    __half* sW = (__half*)smc;                  // [32][520]
    float*  sG = (float*)(smc + LS_GB);         // [64][36]
    const unsigned smu = smem_u32(smc);

    const int j0   = blockIdx.x * JW;
    const int tid  = threadIdx.x;
    const int warp = tid >> 5, lane = tid & 31;
    const int grp  = lane >> 2, tig = lane & 3;
    const int wm = warp & 3;        // m16 tile rows: wm*16
    const int wn = warp >> 2;       // packed cols:   wn*16 (2 n8 tiles)

    const int aoff = (lane & 15) * LSW + (lane >> 4) * 8;
    const int boff = ((lane & 7) + ((lane >> 4) << 3)) * LSW + ((lane >> 3) & 1) * 8;

    // stage W_hh slice (fp16), once per chunk
    for (int idx = tid; idx < PR * 128; idx += 256) {
        int p  = idx >> 7;
        int c4 = (idx & 127) << 2;
        int g  = (p & 3) * HIDDEN + j0 + (p >> 2);
        float4 v = *(const float4*)(Whh + (size_t)g * HIDDEN + c4);
        __half* dw = sW + p * LSW + c4;
        dw[0] = __float2half_rn(v.x); dw[1] = __float2half_rn(v.y);
        dw[2] = __float2half_rn(v.z); dw[3] = __float2half_rn(v.w);
    }
    __syncthreads();

    float cst[2];
    #pragma unroll
    for (int it = 0; it < 2; it++) {
        int id = tid + it * 256;
        int jl = id & 7, b = id >> 3;
        cst[it] = (t0 > 0) ? d_c[b * HIDDEN + j0 + jl] : 0.0f;
    }

    #pragma unroll 1
    for (int t = t0; t < t1; t++) {
        float pg[2][4];
        #pragma unroll
        for (int it = 0; it < 2; it++) {
            int id = tid + it * 256;
            int jl = id & 7, b = id >> 3;
            const float* xp = d_xproj + ((size_t)(t * BATCH + b)) * G4 + j0 + jl;
            pg[it][0] = xp[0];
            pg[it][1] = xp[HIDDEN];
            pg[it][2] = xp[2 * HIDDEN];
            pg[it][3] = xp[3 * HIDDEN];
        }

        float acc[2][4];
        #pragma unroll
        for (int nt = 0; nt < 2; nt++)
            #pragma unroll
            for (int q = 0; q < 4; q++) acc[nt][q] = 0.0f;

        if (t > 0) {
            const __half* A = d_hs + (size_t)(t - 1) * BATCH * HIDDEN;
            #pragma unroll
            for (int half = 0; half < 2; half++) {
                #pragma unroll
                for (int i = 0; i < 8; i++) {
                    int lin = tid + i * 256;           // 0..2047
                    int r = lin >> 5, c16 = lin & 31;  // 64 rows x 32 chunks
                    unsigned dst = smu + (unsigned)(LS_HH + r * LSW + half * 256 + c16 * 8) * 2;
                    cp16(dst, A + (size_t)r * HIDDEN + half * 256 + c16 * 8);
                }
                CP_COMMIT();
            }

            auto mma_half = [&](int half) {
                const int hk = half * 256;
                #pragma unroll
                for (int ks = 0; ks < 256; ks += 16) {
                    unsigned af[4], bf[4];
                    ldsm4(af, smu + (unsigned)(LS_HH + (wm * 16) * LSW + hk + ks + aoff) * 2);
                    ldsm4(bf, smu + (unsigned)((wn * 16) * LSW + hk + ks + boff) * 2);
                    mma_f16(acc[0], af, &bf[0]);
                    mma_f16(acc[1], af, &bf[2]);
                }
            };

            CP_WAIT(1); __syncthreads();
            mma_half(0);
            CP_WAIT(0); __syncthreads();
            mma_half(1);

            __syncthreads();
            #pragma unroll
            for (int nt = 0; nt < 2; nt++) {
                int r  = wm * 16 + grp;
                int cc = wn * 16 + nt * 8 + 2 * tig;
                sG[r * 36 + cc]           = acc[nt][0];
                sG[r * 36 + cc + 1]       = acc[nt][1];
                sG[(r + 8) * 36 + cc]     = acc[nt][2];
                sG[(r + 8) * 36 + cc + 1] = acc[nt][3];
            }
            __syncthreads();
        }

        #pragma unroll
        for (int it = 0; it < 2; it++) {
            int id = tid + it * 256;
            int jl = id & 7, b = id >> 3;
            int j  = j0 + jl;
            float gi = pg[it][0], gf = pg[it][1], gg = pg[it][2], go = pg[it][3];
            if (t > 0) {
                gi += sG[b * 36 + jl * 4 + 0];
                gf += sG[b * 36 + jl * 4 + 1];
                gg += sG[b * 36 + jl * 4 + 2];
                go += sG[b * 36 + jl * 4 + 3];
            }
            float cn = sigf(gf) * cst[it] + sigf(gi) * tanhf(gg);
            float hn = sigf(go) * tanhf(cn);
            cst[it] = cn;
            d_hs[((size_t)t * BATCH + b) * HIDDEN + j] = __float2half_rn(hn);
        }

        if (t < t1 - 1) {          // chunk boundary = kernel boundary barrier
            __syncthreads();
            if (tid == 0) {
                __threadfence();
                atomicAdd(&d_bar[t], 1u);
                while (ld_acq(&d_bar[t]) < NCTA) { }
            }
            __syncthreads();
        }
    }

    // spill cell state for the next chunk
    #pragma unroll
    for (int it = 0; it < 2; it++) {
        int id = tid + it * 256;
        int jl = id & 7, b = id >> 3;
        d_c[b * HIDDEN + j0 + jl] = cst[it];
    }
}

// ---------------- launch ------------------------------------------------------
extern "C" void kernel_launch(void* const* d_in, const int* in_sizes, int n_in,
                              void* d_out, int out_size) {
    const float* features  = (const float*)d_in[0];
    const int*   captions  = (const int*)  d_in[1];
    /* lengths d_in[2] unused by the reference */
    const float* embedding = (const float*)d_in[3];
    const float* W_ih      = (const float*)d_in[4];
    const float* W_hh      = (const float*)d_in[5];
    const float* b_ih      = (const float*)d_in[6];
    const float* b_hh      = (const float*)d_in[7];
    const float* W_out     = (const float*)d_in[8];
    const float* b_out     = (const float*)d_in[9];
    float* out = (float*)d_out;

    __half *xg_p, *hs_p, *wih_p, *wout_p;
    float *xproj_p;
    cudaGetSymbolAddress((void**)&xg_p,    d_xg);
    cudaGetSymbolAddress((void**)&xproj_p, d_xproj);
    cudaGetSymbolAddress((void**)&hs_p,    d_hs);
    cudaGetSymbolAddress((void**)&wih_p,   d_wih_h);
    cudaGetSymbolAddress((void**)&wout_p,  d_wout_h);

    cudaFuncSetAttribute(gemm_h,
                         cudaFuncAttributeMaxDynamicSharedMemorySize, GEMM_SMEM_BYTES);
    cudaFuncSetAttribute(lstm_persist,
                         cudaFuncAttributeMaxDynamicSharedMemorySize, LS_BYTES);

    // one-time side stream + events (resource creation only; no device work cached)
    static cudaStream_t s2 = nullptr;
    static cudaEvent_t evw, evc[4], evj;
    if (!s2) {
        cudaStreamCreateWithFlags(&s2, cudaStreamNonBlocking);
        cudaEventCreateWithFlags(&evw, cudaEventDisableTiming);
        for (int i = 0; i < 4; i++) cudaEventCreateWithFlags(&evc[i], cudaEventDisableTiming);
        cudaEventCreateWithFlags(&evj, cudaEventDisableTiming);
    }

    // fork: W_out fp16 conversion runs on s2, overlapping gather/x_proj/LSTM ch0
    cudaEventRecord(evw, 0);
    cudaStreamWaitEvent(s2, evw, 0);
    roundh<<<(VOCAB * HIDDEN / 4 + 255) / 256, 256, 0, s2>>>(W_out, wout_p,
                                                             VOCAB * HIDDEN / 4);

    // stream 0: gather + W_ih conversion + x_proj + barrier reset
    gather_kernel<<<MROWS, 256>>>(features, captions, embedding);
    roundh<<<(G4 * EMBED / 4 + 255) / 256, 256>>>(W_ih, wih_p, G4 * EMBED / 4);
    {
        dim3 grid(G4 / 128, MPAD / 128);       // (16, 17)
        gemm_h<<<grid, 256, GEMM_SMEM_BYTES>>>(xg_p, wih_p, b_ih, b_hh, xproj_p,
                                               MROWS, G4, EMBED, 0, 0);
    }
    bar_reset<<<1, 64>>>();

    // LSTM in 4 chunks; logits for each chunk's rows overlaps later chunks on s2
    const int t0s[4]   = {0, 8, 16, 24};
    const int t1s[4]   = {8, 16, 24, 33};
    const int tile0[4] = {0, 4, 8, 12};
    const int ntls[4]  = {4, 4, 4, 5};         // last covers rows 1536..2176 (pad)
    for (int ch = 0; ch < 4; ch++) {
        lstm_persist<<<NCTA, 256, LS_BYTES>>>(W_hh, t0s[ch], t1s[ch]);
        cudaEventRecord(evc[ch], 0);
        cudaStreamWaitEvent(s2, evc[ch], 0);
        dim3 grid(VOCAB / 128, ntls[ch]);      // (250, ntiles)
        gemm_h<<<grid, 256, GEMM_SMEM_BYTES, s2>>>(hs_p, wout_p, b_out, nullptr, out,
                                                   MROWS, VOCAB, HIDDEN, 1, tile0[ch]);
    }

    // join: stream 0 (capture stream) waits for all logits work
    cudaEventRecord(evj, s2);
    cudaStreamWaitEvent(0, evj, 0);
}